// round 3
// baseline (speedup 1.0000x reference)
#include <cuda_runtime.h>

// Problem constants
static constexpr int NV    = 65536;   // 16 * 4096 vectors
static constexpr int D     = 64;      // embedding dim
static constexpr int NE    = 1024;    // codebook size
static constexpr int CHUNK = 64;      // codes cached in smem per tile
static constexpr int TPB   = 64;      // threads per block (1 vector / thread)
static constexpr int ZQ_ELEMS = NV * D;   // 4194304

// Scratch (no allocations allowed in kernel_launch)
__device__ int   g_idx[NV];
__device__ float g_norm[NE];

// ---------------------------------------------------------------------------
// Precompute ||e_j||^2
// ---------------------------------------------------------------------------
__global__ void norm_kernel(const float* __restrict__ emb) {
    int j = blockIdx.x * blockDim.x + threadIdx.x;
    if (j < NE) {
        const float4* e4 = reinterpret_cast<const float4*>(emb + j * D);
        float s = 0.f;
        #pragma unroll
        for (int k = 0; k < D / 4; k++) {
            float4 v = e4[k];
            s += v.x * v.x + v.y * v.y + v.z * v.z + v.w * v.w;
        }
        g_norm[j] = s;
    }
}

__global__ void init_kernel(float* __restrict__ out) {
    if (threadIdx.x == 0 && blockIdx.x == 0) out[0] = 0.f;
}

// packed f32x2 FMA / ADD (sm_103a; ptxas never auto-fuses these)
#define FFMA2(d, a, b) \
    asm("fma.rn.f32x2 %0, %1, %2, %0;" : "+l"(d) : "l"(a), "l"(b))
#define FADD2(d, a) \
    asm("add.rn.f32x2 %0, %0, %1;" : "+l"(d) : "l"(a))

// ---------------------------------------------------------------------------
// Argmin kernel: one vector per thread, codebook tiled through smem.
// Reference computes  d = (||z||^2 + ||e||^2) - 2 z.e  in fp32, where
// ||z||^2 ~ 64 dominates -> distances are quantized to ulp(64) ~ 7.6e-6.
// To reproduce argmin tie-breaks exactly, we apply the SAME rounding chain:
//   t1 = ||z||^2 + ||e_j||^2   (fp32 round)
//   d  = fma(-2, z.e_j, t1)    (fp32 single rounding; 2m is exact)
// and scan ascending j with strict '<' (argmin keeps first/lowest index).
// ---------------------------------------------------------------------------
__global__ __launch_bounds__(TPB) void argmin_kernel(
    const float* __restrict__ z,
    const float* __restrict__ emb,
    float* __restrict__ out_idx)   // = d_out + 1 + ZQ_ELEMS
{
    __shared__ float se[CHUNK * D];
    __shared__ float sn[CHUNK];

    const int vec = blockIdx.x * TPB + threadIdx.x;

    // Load this thread's z vector, packed 2 floats per 64-bit register.
    unsigned long long zz[D / 2];
    const unsigned long long* zp =
        reinterpret_cast<const unsigned long long*>(z + (size_t)vec * D);
    #pragma unroll
    for (int k = 0; k < D / 2; k++) zz[k] = zp[k];

    // zn = ||z||^2 (per-row constant; shifts all candidates equally before
    // the final rounding -> matches reference's quantization grid).
    float zn;
    {
        unsigned long long a0 = 0ull, a1 = 0ull, a2 = 0ull, a3 = 0ull;
        #pragma unroll
        for (int k = 0; k < D / 8; k++) {
            FFMA2(a0, zz[4 * k + 0], zz[4 * k + 0]);
            FFMA2(a1, zz[4 * k + 1], zz[4 * k + 1]);
            FFMA2(a2, zz[4 * k + 2], zz[4 * k + 2]);
            FFMA2(a3, zz[4 * k + 3], zz[4 * k + 3]);
        }
        FADD2(a0, a1);
        FADD2(a2, a3);
        FADD2(a0, a2);
        float lo, hi;
        asm("mov.b64 {%0, %1}, %2;" : "=f"(lo), "=f"(hi) : "l"(a0));
        zn = lo + hi;
    }

    float best = 3.4e38f;
    int   bidx = 0;

    for (int c = 0; c < NE / CHUNK; c++) {
        // Cooperative chunk load (codes [c*CHUNK, (c+1)*CHUNK))
        const float4* src = reinterpret_cast<const float4*>(emb + (size_t)c * CHUNK * D);
        float4* dst = reinterpret_cast<float4*>(se);
        #pragma unroll
        for (int k = 0; k < (CHUNK * D / 4) / TPB; k++)
            dst[threadIdx.x + k * TPB] = src[threadIdx.x + k * TPB];
        sn[threadIdx.x] = g_norm[c * CHUNK + threadIdx.x];   // TPB == CHUNK
        __syncthreads();

        #pragma unroll 1
        for (int j = 0; j < CHUNK; j++) {
            const ulonglong2* es = reinterpret_cast<const ulonglong2*>(se + j * D);
            unsigned long long a0 = 0ull, a1 = 0ull, a2 = 0ull, a3 = 0ull;
            #pragma unroll
            for (int k = 0; k < D / 8; k++) {          // 8 iters: 16 LDS.128, 32 FFMA2
                ulonglong2 e0 = es[2 * k];
                ulonglong2 e1 = es[2 * k + 1];
                FFMA2(a0, zz[4 * k + 0], e0.x);
                FFMA2(a1, zz[4 * k + 1], e0.y);
                FFMA2(a2, zz[4 * k + 2], e1.x);
                FFMA2(a3, zz[4 * k + 3], e1.y);
            }
            FADD2(a0, a1);
            FADD2(a2, a3);
            FADD2(a0, a2);
            float lo, hi;
            asm("mov.b64 {%0, %1}, %2;" : "=f"(lo), "=f"(hi) : "l"(a0));
            float t  = lo + hi;                        // z . e_j
            float t1 = zn + sn[j];                     // fp32 round (quantize)
            float dist = fmaf(-2.f, t, t1);            // single-rounded subtract
            if (dist < best) { best = dist; bidx = c * CHUNK + j; }
        }
        __syncthreads();
    }

    g_idx[vec]   = bidx;
    out_idx[vec] = (float)bidx;
}

// ---------------------------------------------------------------------------
// Gather z_q = embedding[idx], exact elementwise loss accumulation.
// loss = 1.25 * mean((z_q - z)^2) over all NV*D elements.
// ---------------------------------------------------------------------------
__global__ void gather_kernel(
    const float* __restrict__ z,
    const float* __restrict__ emb,
    float* __restrict__ out)   // out[0] = loss, out+1 = z_q
{
    const int i = blockIdx.x * 256 + threadIdx.x;
    const int vec = i >> 6;
    const int d   = i & (D - 1);
    const int idx = g_idx[vec];

    float e  = emb[idx * D + d];
    float zv = z[i];
    out[1 + i] = e;

    float df = e - zv;
    float p  = df * df;

    __shared__ float red[256];
    red[threadIdx.x] = p;
    __syncthreads();
    #pragma unroll
    for (int s = 128; s > 0; s >>= 1) {
        if (threadIdx.x < s) red[threadIdx.x] += red[threadIdx.x + s];
        __syncthreads();
    }
    if (threadIdx.x == 0)
        atomicAdd(out, red[0] * (1.25f / (float)ZQ_ELEMS));
}

// ---------------------------------------------------------------------------
extern "C" void kernel_launch(void* const* d_in, const int* in_sizes, int n_in,
                              void* d_out, int out_size) {
    const float* z   = (const float*)d_in[0];   // [16,4096,64]
    const float* emb = (const float*)d_in[1];   // [1024,64]
    float* out = (float*)d_out;                 // [loss | z_q | indices]

    norm_kernel<<<(NE + 127) / 128, 128>>>(emb);
    init_kernel<<<1, 32>>>(out);
    argmin_kernel<<<NV / TPB, TPB>>>(z, emb, out + 1 + ZQ_ELEMS);
    gather_kernel<<<ZQ_ELEMS / 256, 256>>>(z, emb, out);
}

// round 5
// speedup vs baseline: 1.2708x; 1.2708x over previous
#include <cuda_runtime.h>

// Problem constants
static constexpr int NV    = 65536;   // 16 * 4096 vectors
static constexpr int D     = 64;      // embedding dim
static constexpr int NE    = 1024;    // codebook size
static constexpr int CHUNK = 64;      // codes cached in smem per tile
static constexpr int TPB   = 64;      // threads per block
static constexpr int VPT   = 2;       // vectors per thread
static constexpr int ZQ_ELEMS = NV * D;   // 4194304

// Scratch (no allocations allowed in kernel_launch)
__device__ int   g_idx[NV];
__device__ float g_norm[NE];

// ---------------------------------------------------------------------------
// Precompute ||e_j||^2
// ---------------------------------------------------------------------------
__global__ void norm_kernel(const float* __restrict__ emb) {
    int j = blockIdx.x * blockDim.x + threadIdx.x;
    if (j < NE) {
        const float4* e4 = reinterpret_cast<const float4*>(emb + j * D);
        float s = 0.f;
        #pragma unroll
        for (int k = 0; k < D / 4; k++) {
            float4 v = e4[k];
            s += v.x * v.x + v.y * v.y + v.z * v.z + v.w * v.w;
        }
        g_norm[j] = s;
    }
}

__global__ void init_kernel(float* __restrict__ out) {
    if (threadIdx.x == 0 && blockIdx.x == 0) out[0] = 0.f;
}

// packed f32x2 FMA / ADD (sm_103a; ptxas never auto-fuses these)
#define FFMA2(d, a, b) \
    asm("fma.rn.f32x2 %0, %1, %2, %0;" : "+l"(d) : "l"(a), "l"(b))
#define FADD2(d, a) \
    asm("add.rn.f32x2 %0, %0, %1;" : "+l"(d) : "l"(a))

__device__ __forceinline__ float hsum2(unsigned long long a) {
    float lo, hi;
    asm("mov.b64 {%0, %1}, %2;" : "=f"(lo), "=f"(hi) : "l"(a));
    return lo + hi;
}

// ---------------------------------------------------------------------------
// Argmin kernel: TWO vectors per thread (shares every code LDS across 2 dot
// products -> halves the smem-pipe load, leaving FFMA2 as the binding pipe).
//
// Reference computes  d = (||z||^2 + ||e||^2) - 2 z.e  in fp32, where
// ||z||^2 ~ 64 dominates -> distances quantized to ulp(64) ~ 7.6e-6.
// Reproduce the same rounding chain:
//   t1 = ||z||^2 + ||e_j||^2   (fp32 round)
//   d  = fma(-2, z.e_j, t1)    (single rounding)
// and scan ascending j with strict '<' (matches argmin lowest-index ties).
// ---------------------------------------------------------------------------
__global__ __launch_bounds__(TPB) void argmin_kernel(
    const float* __restrict__ z,
    const float* __restrict__ emb,
    float* __restrict__ out_idx)   // = d_out + 1 + ZQ_ELEMS
{
    __shared__ float se[CHUNK * D];
    __shared__ float sn[CHUNK];

    const int t    = threadIdx.x;
    const int vec0 = blockIdx.x * (TPB * VPT) + t;
    const int vec1 = vec0 + TPB;

    // Load both z vectors, packed 2 floats per 64-bit register.
    unsigned long long z0[D / 2], z1[D / 2];
    {
        const unsigned long long* p0 =
            reinterpret_cast<const unsigned long long*>(z + (size_t)vec0 * D);
        const unsigned long long* p1 =
            reinterpret_cast<const unsigned long long*>(z + (size_t)vec1 * D);
        #pragma unroll
        for (int k = 0; k < D / 2; k++) { z0[k] = p0[k]; z1[k] = p1[k]; }
    }

    // zn = ||z||^2 per vector (sets the reference quantization grid).
    float zn0, zn1;
    {
        unsigned long long a0 = 0, a1 = 0, a2 = 0, a3 = 0;
        unsigned long long b0 = 0, b1 = 0, b2 = 0, b3 = 0;
        #pragma unroll
        for (int k = 0; k < D / 8; k++) {
            FFMA2(a0, z0[4 * k + 0], z0[4 * k + 0]);
            FFMA2(a1, z0[4 * k + 1], z0[4 * k + 1]);
            FFMA2(a2, z0[4 * k + 2], z0[4 * k + 2]);
            FFMA2(a3, z0[4 * k + 3], z0[4 * k + 3]);
            FFMA2(b0, z1[4 * k + 0], z1[4 * k + 0]);
            FFMA2(b1, z1[4 * k + 1], z1[4 * k + 1]);
            FFMA2(b2, z1[4 * k + 2], z1[4 * k + 2]);
            FFMA2(b3, z1[4 * k + 3], z1[4 * k + 3]);
        }
        FADD2(a0, a1); FADD2(a2, a3); FADD2(a0, a2);
        FADD2(b0, b1); FADD2(b2, b3); FADD2(b0, b2);
        zn0 = hsum2(a0);
        zn1 = hsum2(b0);
    }

    float best0 = 3.4e38f, best1 = 3.4e38f;
    int   bidx0 = 0,       bidx1 = 0;

    for (int c = 0; c < NE / CHUNK; c++) {
        // Cooperative chunk load (codes [c*CHUNK, (c+1)*CHUNK))
        const float4* src = reinterpret_cast<const float4*>(emb + (size_t)c * CHUNK * D);
        float4* dst = reinterpret_cast<float4*>(se);
        #pragma unroll
        for (int k = 0; k < (CHUNK * D / 4) / TPB; k++)
            dst[t + k * TPB] = src[t + k * TPB];
        sn[t] = g_norm[c * CHUNK + t];   // TPB == CHUNK
        __syncthreads();

        #pragma unroll 1
        for (int j = 0; j < CHUNK; j++) {
            const ulonglong2* es = reinterpret_cast<const ulonglong2*>(se + j * D);
            unsigned long long a0 = 0, a1 = 0, a2 = 0, a3 = 0;
            unsigned long long b0 = 0, b1 = 0, b2 = 0, b3 = 0;
            #pragma unroll
            for (int k = 0; k < D / 8; k++) {      // 16 LDS.128 -> 64 FFMA2
                ulonglong2 e0 = es[2 * k];
                ulonglong2 e1 = es[2 * k + 1];
                FFMA2(a0, z0[4 * k + 0], e0.x);
                FFMA2(b0, z1[4 * k + 0], e0.x);
                FFMA2(a1, z0[4 * k + 1], e0.y);
                FFMA2(b1, z1[4 * k + 1], e0.y);
                FFMA2(a2, z0[4 * k + 2], e1.x);
                FFMA2(b2, z1[4 * k + 2], e1.x);
                FFMA2(a3, z0[4 * k + 3], e1.y);
                FFMA2(b3, z1[4 * k + 3], e1.y);
            }
            FADD2(a0, a1); FADD2(a2, a3); FADD2(a0, a2);
            FADD2(b0, b1); FADD2(b2, b3); FADD2(b0, b2);
            float t0 = hsum2(a0);                  // z0 . e_j
            float t1 = hsum2(b0);                  // z1 . e_j
            float sj = sn[j];
            float d0 = fmaf(-2.f, t0, zn0 + sj);
            float d1 = fmaf(-2.f, t1, zn1 + sj);
            if (d0 < best0) { best0 = d0; bidx0 = c * CHUNK + j; }
            if (d1 < best1) { best1 = d1; bidx1 = c * CHUNK + j; }
        }
        __syncthreads();
    }

    g_idx[vec0]   = bidx0;
    g_idx[vec1]   = bidx1;
    out_idx[vec0] = (float)bidx0;
    out_idx[vec1] = (float)bidx1;
}

// ---------------------------------------------------------------------------
// Gather z_q = embedding[idx] (float4 loads), exact elementwise loss.
// loss = 1.25 * mean((z_q - z)^2) over all NV*D elements.
// z_q stores are scalar because out+1 is only 4-byte aligned.
// ---------------------------------------------------------------------------
__global__ void gather_kernel(
    const float* __restrict__ z,
    const float* __restrict__ emb,
    float* __restrict__ out)   // out[0] = loss, out+1 = z_q
{
    const int i4  = blockIdx.x * 256 + threadIdx.x;   // float4 index
    const int vec = i4 >> 4;                          // 16 float4 per vector
    const int d4  = i4 & 15;
    const int idx = g_idx[vec];

    float4 e  = reinterpret_cast<const float4*>(emb)[idx * (D / 4) + d4];
    float4 zv = reinterpret_cast<const float4*>(z)[i4];

    float* o = out + 1 + i4 * 4;
    o[0] = e.x; o[1] = e.y; o[2] = e.z; o[3] = e.w;

    float dx = e.x - zv.x, dy = e.y - zv.y, dz = e.z - zv.z, dw = e.w - zv.w;
    float p = dx * dx + dy * dy + dz * dz + dw * dw;

    // warp reduce
    #pragma unroll
    for (int o2 = 16; o2 > 0; o2 >>= 1)
        p += __shfl_xor_sync(0xFFFFFFFFu, p, o2);

    __shared__ float red[8];
    if ((threadIdx.x & 31) == 0) red[threadIdx.x >> 5] = p;
    __syncthreads();
    if (threadIdx.x == 0) {
        float s = 0.f;
        #pragma unroll
        for (int w = 0; w < 8; w++) s += red[w];
        atomicAdd(out, s * (1.25f / (float)ZQ_ELEMS));
    }
}

// ---------------------------------------------------------------------------
extern "C" void kernel_launch(void* const* d_in, const int* in_sizes, int n_in,
                              void* d_out, int out_size) {
    const float* z   = (const float*)d_in[0];   // [16,4096,64]
    const float* emb = (const float*)d_in[1];   // [1024,64]
    float* out = (float*)d_out;                 // [loss | z_q | indices]

    norm_kernel<<<(NE + 127) / 128, 128>>>(emb);
    init_kernel<<<1, 32>>>(out);
    argmin_kernel<<<NV / (TPB * VPT), TPB>>>(z, emb, out + 1 + ZQ_ELEMS);
    gather_kernel<<<(ZQ_ELEMS / 4) / 256, 256>>>(z, emb, out);
}